// round 3
// baseline (speedup 1.0000x reference)
#include <cuda_runtime.h>
#include <cuda_bf16.h>
#include <cstdint>

#define N_NODES 50000
#define N_EDGES 800000
#define IN_DIM 256
#define OUT_DIM 64

// Scratch (float4-typed for guaranteed 16B alignment)
__device__ float4 g_H4[N_NODES * OUT_DIM / 4];    // H = X@W^T + b
__device__ float4 g_AGG4[N_NODES * OUT_DIM / 4];  // aggregated output
__device__ int    g_deg[N_NODES];
__device__ float  g_dinv[N_NODES];

// ---------------------------------------------------------------------------
// 1) zero degree counters
__global__ void k_zero_deg(int n) {
    int i = blockIdx.x * blockDim.x + threadIdx.x;
    if (i < n) g_deg[i] = 0;
}

// 2) degree histogram over dst
__global__ void k_count_deg(const int* __restrict__ dst, int e) {
    int i = blockIdx.x * blockDim.x + threadIdx.x;
    if (i < e) atomicAdd(&g_deg[dst[i]], 1);
}

// 3) dinv = rsqrt(deg + 1)
__global__ void k_dinv(int n) {
    int i = blockIdx.x * blockDim.x + threadIdx.x;
    if (i < n) g_dinv[i] = rsqrtf((float)g_deg[i] + 1.0f);
}

// ---------------------------------------------------------------------------
// 4) GEMM: H = X @ W^T + b, plus AGG = H * dinv^2 (self-loop seed)
//    Block: 256 threads handles 64 nodes x 64 cols. K chunked by 64.
#define KC 64
__global__ void k_gemm(const float* __restrict__ X, const float* __restrict__ W,
                       const float* __restrict__ b, int n) {
    __shared__ float Xs[KC][65];   // Xs[k][node_local]
    __shared__ float Ws[KC][68];   // Ws[k][col], padded so rows stay 16B aligned

    int tid = threadIdx.x;
    int nodeBase = blockIdx.x * 64;
    int nl = tid >> 2;     // 0..63 local node
    int cg = tid & 3;      // col group: cols [cg*16, cg*16+16)
    int node = nodeBase + nl;

    float acc[16];
#pragma unroll
    for (int c = 0; c < 16; c++) acc[c] = 0.0f;

    for (int kb = 0; kb < IN_DIM; kb += KC) {
        // load X tile transposed: Xs[k][row]
#pragma unroll
        for (int i = 0; i < 4; i++) {
            int idx = tid + i * 256;       // 0..1023
            int row = idx >> 4;            // 0..63
            int k4  = idx & 15;            // 0..15
            int grow = nodeBase + row;
            float4 v = make_float4(0.f, 0.f, 0.f, 0.f);
            if (grow < n)
                v = *(const float4*)&X[grow * IN_DIM + kb + k4 * 4];
            Xs[k4 * 4 + 0][row] = v.x;
            Xs[k4 * 4 + 1][row] = v.y;
            Xs[k4 * 4 + 2][row] = v.z;
            Xs[k4 * 4 + 3][row] = v.w;
        }
        // load W tile transposed: Ws[k][c] from W[c][kb+k]
#pragma unroll
        for (int i = 0; i < 4; i++) {
            int idx = tid + i * 256;
            int c  = idx >> 4;             // 0..63
            int k4 = idx & 15;
            float4 v = *(const float4*)&W[c * IN_DIM + kb + k4 * 4];
            Ws[k4 * 4 + 0][c] = v.x;
            Ws[k4 * 4 + 1][c] = v.y;
            Ws[k4 * 4 + 2][c] = v.z;
            Ws[k4 * 4 + 3][c] = v.w;
        }
        __syncthreads();

#pragma unroll
        for (int k = 0; k < KC; k++) {
            float x = Xs[k][nl];
            const float4* wr = (const float4*)&Ws[k][cg * 16];
#pragma unroll
            for (int c4 = 0; c4 < 4; c4++) {
                float4 w4 = wr[c4];
                acc[c4 * 4 + 0] += x * w4.x;
                acc[c4 * 4 + 1] += x * w4.y;
                acc[c4 * 4 + 2] += x * w4.z;
                acc[c4 * 4 + 3] += x * w4.w;
            }
        }
        __syncthreads();
    }

    if (node < n) {
        float dv = g_dinv[node];
        float selfw = dv * dv;
        float* H   = (float*)g_H4;
        float* AGG = (float*)g_AGG4;
        int base = node * OUT_DIM + cg * 16;
#pragma unroll
        for (int c4 = 0; c4 < 4; c4++) {
            float4 h;
            h.x = acc[c4 * 4 + 0] + b[cg * 16 + c4 * 4 + 0];
            h.y = acc[c4 * 4 + 1] + b[cg * 16 + c4 * 4 + 1];
            h.z = acc[c4 * 4 + 2] + b[cg * 16 + c4 * 4 + 2];
            h.w = acc[c4 * 4 + 3] + b[cg * 16 + c4 * 4 + 3];
            *(float4*)&H[base + c4 * 4] = h;
            float4 a = make_float4(h.x * selfw, h.y * selfw, h.z * selfw, h.w * selfw);
            *(float4*)&AGG[base + c4 * 4] = a;
        }
    }
}

// ---------------------------------------------------------------------------
// 5) edge scatter: AGG[dst] += H[src] * dinv[src]*dinv[dst]
//    16 threads per edge, each thread a float4 column chunk; vector red.
__global__ void k_scatter(const int* __restrict__ src, const int* __restrict__ dst, int e) {
    long long t = (long long)blockIdx.x * blockDim.x + threadIdx.x;
    int edge = (int)(t >> 4);
    int q = (int)(t & 15);
    if (edge >= e) return;
    int s = src[edge];
    int d = dst[edge];
    float norm = g_dinv[s] * g_dinv[d];
    const float* H = (const float*)g_H4;
    float4 h = *(const float4*)&H[s * OUT_DIM + q * 4];
    float4 m = make_float4(h.x * norm, h.y * norm, h.z * norm, h.w * norm);
    float* p = ((float*)g_AGG4) + d * OUT_DIM + q * 4;
    unsigned long long gp = (unsigned long long)__cvta_generic_to_global(p);
    asm volatile("red.global.add.v4.f32 [%0], {%1, %2, %3, %4};"
                 :: "l"(gp), "f"(m.x), "f"(m.y), "f"(m.z), "f"(m.w)
                 : "memory");
}

// ---------------------------------------------------------------------------
// 6) finalize: ReLU + JAX threefry dropout, PARTITIONABLE scheme, 32-bit path:
//    bits[i] = out0 XOR out1 of threefry2x32(key=(0,42), counter=(hi=0, lo=i));
//    keep iff bits>>31 == 0 (uniform < 0.5).
__device__ __forceinline__ uint32_t threefry_xor(uint32_t c0, uint32_t c1) {
    const uint32_t k0 = 0u, k1 = 42u;
    const uint32_t k2 = k0 ^ k1 ^ 0x1BD11BDAu;
    uint32_t x0 = c0 + k0;
    uint32_t x1 = c1 + k1;
#define TF_RND(r) { x0 += x1; x1 = (x1 << (r)) | (x1 >> (32 - (r))); x1 ^= x0; }
    TF_RND(13) TF_RND(15) TF_RND(26) TF_RND(6)
    x0 += k1; x1 += k2 + 1u;
    TF_RND(17) TF_RND(29) TF_RND(16) TF_RND(24)
    x0 += k2; x1 += k0 + 2u;
    TF_RND(13) TF_RND(15) TF_RND(26) TF_RND(6)
    x0 += k0; x1 += k1 + 3u;
    TF_RND(17) TF_RND(29) TF_RND(16) TF_RND(24)
    x0 += k1; x1 += k2 + 4u;
    TF_RND(13) TF_RND(15) TF_RND(26) TF_RND(6)
    x0 += k2; x1 += k0 + 5u;
#undef TF_RND
    return x0 ^ x1;   // JAX 32-bit partitionable path: bits1 ^ bits2
}

__global__ void k_finalize(float* __restrict__ out, int total4) {
    int i4 = blockIdx.x * blockDim.x + threadIdx.x;   // float4 group index
    if (i4 >= total4) return;
    float4 a = g_AGG4[i4];
    uint32_t base = (uint32_t)i4 * 4u;
    uint32_t r0 = threefry_xor(0u, base + 0u);
    uint32_t r1 = threefry_xor(0u, base + 1u);
    uint32_t r2 = threefry_xor(0u, base + 2u);
    uint32_t r3 = threefry_xor(0u, base + 3u);
    float4 o;
    o.x = (r0 & 0x80000000u) ? 0.0f : 2.0f * fmaxf(a.x, 0.0f);
    o.y = (r1 & 0x80000000u) ? 0.0f : 2.0f * fmaxf(a.y, 0.0f);
    o.z = (r2 & 0x80000000u) ? 0.0f : 2.0f * fmaxf(a.z, 0.0f);
    o.w = (r3 & 0x80000000u) ? 0.0f : 2.0f * fmaxf(a.w, 0.0f);
    ((float4*)out)[i4] = o;
}

// ---------------------------------------------------------------------------
extern "C" void kernel_launch(void* const* d_in, const int* in_sizes, int n_in,
                              void* d_out, int out_size) {
    const float* X  = (const float*)d_in[0];
    const float* W  = (const float*)d_in[1];
    const float* b  = (const float*)d_in[2];
    const int* src  = (const int*)d_in[3];
    const int* dst  = (const int*)d_in[4];
    float* out = (float*)d_out;

    int n = in_sizes[0] / IN_DIM;   // 50000
    int e = in_sizes[3];            // 800000
    int total4 = n * OUT_DIM / 4;

    k_zero_deg<<<(n + 255) / 256, 256>>>(n);
    k_count_deg<<<(e + 255) / 256, 256>>>(dst, e);
    k_dinv<<<(n + 255) / 256, 256>>>(n);
    k_gemm<<<(n + 63) / 64, 256>>>(X, W, b, n);
    long long sth = (long long)e * 16;
    k_scatter<<<(unsigned)((sth + 255) / 256), 256>>>(src, dst, e);
    k_finalize<<<(total4 + 255) / 256, 256>>>(out, total4);
}

// round 4
// speedup vs baseline: 2.2226x; 2.2226x over previous
#include <cuda_runtime.h>
#include <cuda_bf16.h>
#include <cstdint>

#define N_NODES 50000
#define N_EDGES 800000
#define IN_DIM 256
#define OUT_DIM 64

// Scratch (float4-typed for guaranteed 16B alignment)
__device__ float4 g_H4[(N_NODES + 128) * OUT_DIM / 4];    // H = X@W^T + b
__device__ float4 g_AGG4[(N_NODES + 128) * OUT_DIM / 4];  // aggregated output
__device__ int    g_deg[N_NODES];
__device__ float  g_dinv[N_NODES];

// ---------------------------------------------------------------------------
// 1) zero degree counters
__global__ void k_zero_deg(int n) {
    int i = blockIdx.x * blockDim.x + threadIdx.x;
    if (i < n) g_deg[i] = 0;
}

// 2) degree histogram over dst
__global__ void k_count_deg(const int* __restrict__ dst, int e) {
    int i = blockIdx.x * blockDim.x + threadIdx.x;
    if (i < e) atomicAdd(&g_deg[dst[i]], 1);
}

// 3) dinv = rsqrt(deg + 1)
__global__ void k_dinv(int n) {
    int i = blockIdx.x * blockDim.x + threadIdx.x;
    if (i < n) g_dinv[i] = rsqrtf((float)g_deg[i] + 1.0f);
}

// ---------------------------------------------------------------------------
// 4) GEMM: H = X @ W^T + b, plus AGG = H * dinv^2 (self-loop seed)
//    Register-blocked: block tile 128 nodes x 64 cols, 128 threads,
//    8x8 output tile per thread. K chunked by 32.
#define BM 128
#define BN 64
#define KC 32
#define TM 8
#define TN 8

__global__ __launch_bounds__(128) void k_gemm(const float* __restrict__ X,
                                              const float* __restrict__ W,
                                              const float* __restrict__ b, int n) {
    __shared__ float Xs[KC][BM + 4];   // Xs[k][row]
    __shared__ float Ws[KC][BN + 4];   // Ws[k][col]

    int tid = threadIdx.x;
    int tx = tid & 7;        // 0..7  -> col group
    int ty = tid >> 3;       // 0..15 -> row group
    int rowBase = ty * TM;
    int colBase = tx * TN;
    int nodeBase = blockIdx.x * BM;

    float acc[TM][TN];
#pragma unroll
    for (int i = 0; i < TM; i++)
#pragma unroll
        for (int j = 0; j < TN; j++) acc[i][j] = 0.0f;

    for (int kb = 0; kb < IN_DIM; kb += KC) {
        // --- load X tile: thread 'tid' owns global row nodeBase+tid ---
        {
            int grow = nodeBase + tid;
            bool ok = grow < n;
            const float4* xr = (const float4*)&X[(long long)grow * IN_DIM + kb];
#pragma unroll
            for (int j = 0; j < KC / 4; j++) {
                float4 v = ok ? xr[j] : make_float4(0.f, 0.f, 0.f, 0.f);
                Xs[j * 4 + 0][tid] = v.x;
                Xs[j * 4 + 1][tid] = v.y;
                Xs[j * 4 + 2][tid] = v.z;
                Xs[j * 4 + 3][tid] = v.w;
            }
        }
        // --- load W tile: 2 threads per output col, 16 k-values each ---
        {
            int col = tid >> 1;
            int koff = (tid & 1) * 16;
            const float4* wr = (const float4*)&W[col * IN_DIM + kb + koff];
#pragma unroll
            for (int j = 0; j < 4; j++) {
                float4 v = wr[j];
                Ws[koff + j * 4 + 0][col] = v.x;
                Ws[koff + j * 4 + 1][col] = v.y;
                Ws[koff + j * 4 + 2][col] = v.z;
                Ws[koff + j * 4 + 3][col] = v.w;
            }
        }
        __syncthreads();

#pragma unroll
        for (int k = 0; k < KC; k++) {
            float4 xa = *(const float4*)&Xs[k][rowBase];
            float4 xb = *(const float4*)&Xs[k][rowBase + 4];
            float4 wa = *(const float4*)&Ws[k][colBase];
            float4 wb = *(const float4*)&Ws[k][colBase + 4];
            float xv[TM] = {xa.x, xa.y, xa.z, xa.w, xb.x, xb.y, xb.z, xb.w};
            float wv[TN] = {wa.x, wa.y, wa.z, wa.w, wb.x, wb.y, wb.z, wb.w};
#pragma unroll
            for (int i = 0; i < TM; i++)
#pragma unroll
                for (int j = 0; j < TN; j++)
                    acc[i][j] += xv[i] * wv[j];
        }
        __syncthreads();
    }

    // epilogue: add bias, write H, seed AGG with self-loop term
    float4 ba = *(const float4*)&b[colBase];
    float4 bb = *(const float4*)&b[colBase + 4];
    float bv[TN] = {ba.x, ba.y, ba.z, ba.w, bb.x, bb.y, bb.z, bb.w};
    float* H   = (float*)g_H4;
    float* AGG = (float*)g_AGG4;
#pragma unroll
    for (int i = 0; i < TM; i++) {
        int node = nodeBase + rowBase + i;
        if (node >= n) break;
        float dv = g_dinv[node];
        float selfw = dv * dv;
        long long base = (long long)node * OUT_DIM + colBase;
        float4 h0, h1, a0, a1;
        h0.x = acc[i][0] + bv[0]; h0.y = acc[i][1] + bv[1];
        h0.z = acc[i][2] + bv[2]; h0.w = acc[i][3] + bv[3];
        h1.x = acc[i][4] + bv[4]; h1.y = acc[i][5] + bv[5];
        h1.z = acc[i][6] + bv[6]; h1.w = acc[i][7] + bv[7];
        a0 = make_float4(h0.x * selfw, h0.y * selfw, h0.z * selfw, h0.w * selfw);
        a1 = make_float4(h1.x * selfw, h1.y * selfw, h1.z * selfw, h1.w * selfw);
        *(float4*)&H[base]       = h0;
        *(float4*)&H[base + 4]   = h1;
        *(float4*)&AGG[base]     = a0;
        *(float4*)&AGG[base + 4] = a1;
    }
}

// ---------------------------------------------------------------------------
// 5) edge scatter: AGG[dst] += H[src] * dinv[src]*dinv[dst]
//    16 threads per edge, each thread a float4 column chunk; vector red.
__global__ void k_scatter(const int* __restrict__ src, const int* __restrict__ dst, int e) {
    long long t = (long long)blockIdx.x * blockDim.x + threadIdx.x;
    int edge = (int)(t >> 4);
    int q = (int)(t & 15);
    if (edge >= e) return;
    int s = src[edge];
    int d = dst[edge];
    float norm = g_dinv[s] * g_dinv[d];
    const float* H = (const float*)g_H4;
    float4 h = *(const float4*)&H[s * OUT_DIM + q * 4];
    float4 m = make_float4(h.x * norm, h.y * norm, h.z * norm, h.w * norm);
    float* p = ((float*)g_AGG4) + d * OUT_DIM + q * 4;
    unsigned long long gp = (unsigned long long)__cvta_generic_to_global(p);
    asm volatile("red.global.add.v4.f32 [%0], {%1, %2, %3, %4};"
                 :: "l"(gp), "f"(m.x), "f"(m.y), "f"(m.z), "f"(m.w)
                 : "memory");
}

// ---------------------------------------------------------------------------
// 6) finalize: ReLU + JAX threefry dropout, PARTITIONABLE scheme, 32-bit path:
//    bits[i] = out0 XOR out1 of threefry2x32(key=(0,42), counter=(hi=0, lo=i));
//    keep iff bits>>31 == 0 (uniform < 0.5).
__device__ __forceinline__ uint32_t threefry_xor(uint32_t c0, uint32_t c1) {
    const uint32_t k0 = 0u, k1 = 42u;
    const uint32_t k2 = k0 ^ k1 ^ 0x1BD11BDAu;
    uint32_t x0 = c0 + k0;
    uint32_t x1 = c1 + k1;
#define TF_RND(r) { x0 += x1; x1 = (x1 << (r)) | (x1 >> (32 - (r))); x1 ^= x0; }
    TF_RND(13) TF_RND(15) TF_RND(26) TF_RND(6)
    x0 += k1; x1 += k2 + 1u;
    TF_RND(17) TF_RND(29) TF_RND(16) TF_RND(24)
    x0 += k2; x1 += k0 + 2u;
    TF_RND(13) TF_RND(15) TF_RND(26) TF_RND(6)
    x0 += k0; x1 += k1 + 3u;
    TF_RND(17) TF_RND(29) TF_RND(16) TF_RND(24)
    x0 += k1; x1 += k2 + 4u;
    TF_RND(13) TF_RND(15) TF_RND(26) TF_RND(6)
    x0 += k2; x1 += k0 + 5u;
#undef TF_RND
    return x0 ^ x1;   // JAX 32-bit partitionable path: bits1 ^ bits2
}

__global__ void k_finalize(float* __restrict__ out, int total4) {
    int i4 = blockIdx.x * blockDim.x + threadIdx.x;   // float4 group index
    if (i4 >= total4) return;
    float4 a = g_AGG4[i4];
    uint32_t base = (uint32_t)i4 * 4u;
    uint32_t r0 = threefry_xor(0u, base + 0u);
    uint32_t r1 = threefry_xor(0u, base + 1u);
    uint32_t r2 = threefry_xor(0u, base + 2u);
    uint32_t r3 = threefry_xor(0u, base + 3u);
    float4 o;
    o.x = (r0 & 0x80000000u) ? 0.0f : 2.0f * fmaxf(a.x, 0.0f);
    o.y = (r1 & 0x80000000u) ? 0.0f : 2.0f * fmaxf(a.y, 0.0f);
    o.z = (r2 & 0x80000000u) ? 0.0f : 2.0f * fmaxf(a.z, 0.0f);
    o.w = (r3 & 0x80000000u) ? 0.0f : 2.0f * fmaxf(a.w, 0.0f);
    ((float4*)out)[i4] = o;
}

// ---------------------------------------------------------------------------
extern "C" void kernel_launch(void* const* d_in, const int* in_sizes, int n_in,
                              void* d_out, int out_size) {
    const float* X  = (const float*)d_in[0];
    const float* W  = (const float*)d_in[1];
    const float* b  = (const float*)d_in[2];
    const int* src  = (const int*)d_in[3];
    const int* dst  = (const int*)d_in[4];
    float* out = (float*)d_out;

    int n = in_sizes[0] / IN_DIM;   // 50000
    int e = in_sizes[3];            // 800000
    int total4 = n * OUT_DIM / 4;

    k_zero_deg<<<(n + 255) / 256, 256>>>(n);
    k_count_deg<<<(e + 255) / 256, 256>>>(dst, e);
    k_dinv<<<(n + 255) / 256, 256>>>(n);
    k_gemm<<<(n + BM - 1) / BM, 128>>>(X, W, b, n);
    long long sth = (long long)e * 16;
    k_scatter<<<(unsigned)((sth + 255) / 256), 256>>>(src, dst, e);
    k_finalize<<<(total4 + 255) / 256, 256>>>(out, total4);
}

// round 5
// speedup vs baseline: 2.9623x; 1.3328x over previous
#include <cuda_runtime.h>
#include <cuda_bf16.h>
#include <cstdint>

#define N_NODES 50000
#define N_EDGES 800000
#define IN_DIM 256
#define OUT_DIM 64

// Scratch
__device__ float4 g_H4[(N_NODES + 128) * OUT_DIM / 4];  // Hs = (X@W^T + b) * dinv[node]
__device__ int    g_deg[N_NODES];
__device__ float  g_dinv[N_NODES];
__device__ int    g_part[N_NODES + 64];   // per-block-scanned partial prefix
__device__ int    g_btot[64];
__device__ int    g_boff[64];
__device__ int    g_rowptr[N_NODES];
__device__ int    g_cursor[N_NODES];
__device__ int    g_esrc[N_EDGES];

// ---------------------------------------------------------------------------
// degree histogram over dst (deg zeroed via memset on the symbol)
__global__ void k_count_deg(const int* __restrict__ dst, int e) {
    int i = blockIdx.x * blockDim.x + threadIdx.x;
    if (i < e) atomicAdd(&g_deg[dst[i]], 1);
}

// scan phase 1: each block scans 1024 degs -> g_part (block-local exclusive), g_btot
__global__ void k_scan1(int n) {
    __shared__ int ts[256];
    int tid = threadIdx.x;
    int base = blockIdx.x * 1024 + tid * 4;
    int v0 = (base + 0 < n) ? g_deg[base + 0] : 0;
    int v1 = (base + 1 < n) ? g_deg[base + 1] : 0;
    int v2 = (base + 2 < n) ? g_deg[base + 2] : 0;
    int v3 = (base + 3 < n) ? g_deg[base + 3] : 0;
    int s = v0 + v1 + v2 + v3;
    ts[tid] = s;
    __syncthreads();
    for (int off = 1; off < 256; off <<= 1) {
        int x = (tid >= off) ? ts[tid - off] : 0;
        __syncthreads();
        ts[tid] += x;
        __syncthreads();
    }
    int ex = ts[tid] - s;  // exclusive prefix of this thread's chunk
    if (base + 0 < n + 4) {  // g_part padded; guard loosely then strictly below
        if (base + 0 < n) g_part[base + 0] = ex;
        if (base + 1 < n) g_part[base + 1] = ex + v0;
        if (base + 2 < n) g_part[base + 2] = ex + v0 + v1;
        if (base + 3 < n) g_part[base + 3] = ex + v0 + v1 + v2;
    }
    if (tid == 255) g_btot[blockIdx.x] = ts[255];
}

// scan phase 2: single block, exclusive scan of block totals
__global__ void k_scan2(int nblocks) {
    __shared__ int ts[64];
    int tid = threadIdx.x;
    int v = (tid < nblocks) ? g_btot[tid] : 0;
    ts[tid] = v;
    __syncthreads();
    for (int off = 1; off < 64; off <<= 1) {
        int x = (tid >= off) ? ts[tid - off] : 0;
        __syncthreads();
        ts[tid] += x;
        __syncthreads();
    }
    g_boff[tid] = ts[tid] - v;
}

// scan phase 3: finalize rowptr, cursor, dinv
__global__ void k_scan3(int n) {
    int i = blockIdx.x * blockDim.x + threadIdx.x;
    if (i >= n) return;
    int rp = g_part[i] + g_boff[i >> 10];
    g_rowptr[i] = rp;
    g_cursor[i] = rp;
    g_dinv[i] = rsqrtf((float)g_deg[i] + 1.0f);
}

// CSR fill: bucket edge sources by dst
__global__ void k_fill(const int* __restrict__ src, const int* __restrict__ dst, int e) {
    int i = blockIdx.x * blockDim.x + threadIdx.x;
    if (i >= e) return;
    int d = dst[i];
    int pos = atomicAdd(&g_cursor[d], 1);
    g_esrc[pos] = src[i];
}

// ---------------------------------------------------------------------------
// GEMM: Hs = (X @ W^T + b) * dinv[node]
// 256 threads, block tile 128x64, per-thread 8 rows x 4 cols. K chunked by 32.
#define BM 128
#define BN 64
#define KC 32

__global__ __launch_bounds__(256) void k_gemm(const float* __restrict__ X,
                                              const float* __restrict__ W,
                                              const float* __restrict__ b, int n) {
    __shared__ float Xs[KC][BM + 4];
    __shared__ float Ws[KC][BN + 4];

    int tid = threadIdx.x;
    int tx = tid & 15;       // 0..15 -> colBase = tx*4
    int ty = tid >> 4;       // 0..15 -> rowBase = ty*8
    int rowBase = ty * 8;
    int colBase = tx * 4;
    int nodeBase = blockIdx.x * BM;

    float acc[8][4];
#pragma unroll
    for (int i = 0; i < 8; i++)
#pragma unroll
        for (int j = 0; j < 4; j++) acc[i][j] = 0.0f;

    for (int kb = 0; kb < IN_DIM; kb += KC) {
        // X tile: 128 rows x 32 k. 2 threads/row, 16 consecutive k each.
        {
            int xrow = tid >> 1;
            int xk = (tid & 1) * 16;
            int grow = nodeBase + xrow;
            bool ok = grow < n;
            const float4* xr = (const float4*)&X[(long long)grow * IN_DIM + kb + xk];
#pragma unroll
            for (int j = 0; j < 4; j++) {
                float4 v = ok ? xr[j] : make_float4(0.f, 0.f, 0.f, 0.f);
                Xs[xk + j * 4 + 0][xrow] = v.x;
                Xs[xk + j * 4 + 1][xrow] = v.y;
                Xs[xk + j * 4 + 2][xrow] = v.z;
                Xs[xk + j * 4 + 3][xrow] = v.w;
            }
        }
        // W tile: 64 cols x 32 k. 4 threads/col, 8 consecutive k each.
        {
            int wcol = tid >> 2;
            int wk = (tid & 3) * 8;
            const float4* wr = (const float4*)&W[wcol * IN_DIM + kb + wk];
#pragma unroll
            for (int j = 0; j < 2; j++) {
                float4 v = wr[j];
                Ws[wk + j * 4 + 0][wcol] = v.x;
                Ws[wk + j * 4 + 1][wcol] = v.y;
                Ws[wk + j * 4 + 2][wcol] = v.z;
                Ws[wk + j * 4 + 3][wcol] = v.w;
            }
        }
        __syncthreads();

#pragma unroll
        for (int k = 0; k < KC; k++) {
            float4 xa = *(const float4*)&Xs[k][rowBase];
            float4 xb = *(const float4*)&Xs[k][rowBase + 4];
            float4 wa = *(const float4*)&Ws[k][colBase];
            float xv[8] = {xa.x, xa.y, xa.z, xa.w, xb.x, xb.y, xb.z, xb.w};
            float wv[4] = {wa.x, wa.y, wa.z, wa.w};
#pragma unroll
            for (int i = 0; i < 8; i++)
#pragma unroll
                for (int j = 0; j < 4; j++)
                    acc[i][j] += xv[i] * wv[j];
        }
        __syncthreads();
    }

    // epilogue: Hs = (acc + b) * dinv
    float4 bva = *(const float4*)&b[colBase];
    float bv[4] = {bva.x, bva.y, bva.z, bva.w};
    float* Hs = (float*)g_H4;
#pragma unroll
    for (int i = 0; i < 8; i++) {
        int node = nodeBase + rowBase + i;
        if (node >= n) break;
        float dv = g_dinv[node];
        float4 h;
        h.x = (acc[i][0] + bv[0]) * dv;
        h.y = (acc[i][1] + bv[1]) * dv;
        h.z = (acc[i][2] + bv[2]) * dv;
        h.w = (acc[i][3] + bv[3]) * dv;
        *(float4*)&Hs[(long long)node * OUT_DIM + colBase] = h;
    }
}

// ---------------------------------------------------------------------------
// threefry: JAX partitionable 32-bit path: bits = out0 ^ out1, counter (0, i)
__device__ __forceinline__ uint32_t threefry_xor(uint32_t c0, uint32_t c1) {
    const uint32_t k0 = 0u, k1 = 42u;
    const uint32_t k2 = k0 ^ k1 ^ 0x1BD11BDAu;
    uint32_t x0 = c0 + k0;
    uint32_t x1 = c1 + k1;
#define TF_RND(r) { x0 += x1; x1 = (x1 << (r)) | (x1 >> (32 - (r))); x1 ^= x0; }
    TF_RND(13) TF_RND(15) TF_RND(26) TF_RND(6)
    x0 += k1; x1 += k2 + 1u;
    TF_RND(17) TF_RND(29) TF_RND(16) TF_RND(24)
    x0 += k2; x1 += k0 + 2u;
    TF_RND(13) TF_RND(15) TF_RND(26) TF_RND(6)
    x0 += k0; x1 += k1 + 3u;
    TF_RND(17) TF_RND(29) TF_RND(16) TF_RND(24)
    x0 += k1; x1 += k2 + 4u;
    TF_RND(13) TF_RND(15) TF_RND(26) TF_RND(6)
    x0 += k2; x1 += k0 + 5u;
#undef TF_RND
    return x0 ^ x1;
}

// ---------------------------------------------------------------------------
// Gather + self-loop + dinv[dst] + ReLU + dropout, fully fused.
// 16 threads per node, each owns one float4 column chunk.
__global__ __launch_bounds__(256) void k_gather(float* __restrict__ out, int n) {
    int t = blockIdx.x * blockDim.x + threadIdx.x;
    int node = t >> 4;
    int q = t & 15;
    if (node >= n) return;

    const float4* Hs = g_H4;
    int beg = g_rowptr[node];
    int cnt = g_deg[node];
    int end = beg + cnt;

    float4 acc = Hs[node * 16 + q];  // self term (already *dinv[node])
    int j = beg;
    for (; j + 4 <= end; j += 4) {
        int s0 = g_esrc[j + 0];
        int s1 = g_esrc[j + 1];
        int s2 = g_esrc[j + 2];
        int s3 = g_esrc[j + 3];
        float4 a0 = Hs[s0 * 16 + q];
        float4 a1 = Hs[s1 * 16 + q];
        float4 a2 = Hs[s2 * 16 + q];
        float4 a3 = Hs[s3 * 16 + q];
        acc.x += (a0.x + a1.x) + (a2.x + a3.x);
        acc.y += (a0.y + a1.y) + (a2.y + a3.y);
        acc.z += (a0.z + a1.z) + (a2.z + a3.z);
        acc.w += (a0.w + a1.w) + (a2.w + a3.w);
    }
    for (; j < end; j++) {
        float4 a = Hs[g_esrc[j] * 16 + q];
        acc.x += a.x; acc.y += a.y; acc.z += a.z; acc.w += a.w;
    }

    float dv = g_dinv[node];
    acc.x *= dv; acc.y *= dv; acc.z *= dv; acc.w *= dv;

    uint32_t base = (uint32_t)(node * OUT_DIM + q * 4);
    uint32_t r0 = threefry_xor(0u, base + 0u);
    uint32_t r1 = threefry_xor(0u, base + 1u);
    uint32_t r2 = threefry_xor(0u, base + 2u);
    uint32_t r3 = threefry_xor(0u, base + 3u);
    float4 o;
    o.x = (r0 & 0x80000000u) ? 0.0f : 2.0f * fmaxf(acc.x, 0.0f);
    o.y = (r1 & 0x80000000u) ? 0.0f : 2.0f * fmaxf(acc.y, 0.0f);
    o.z = (r2 & 0x80000000u) ? 0.0f : 2.0f * fmaxf(acc.z, 0.0f);
    o.w = (r3 & 0x80000000u) ? 0.0f : 2.0f * fmaxf(acc.w, 0.0f);
    ((float4*)out)[node * 16 + q] = o;
}

// ---------------------------------------------------------------------------
extern "C" void kernel_launch(void* const* d_in, const int* in_sizes, int n_in,
                              void* d_out, int out_size) {
    const float* X  = (const float*)d_in[0];
    const float* W  = (const float*)d_in[1];
    const float* b  = (const float*)d_in[2];
    const int* src  = (const int*)d_in[3];
    const int* dst  = (const int*)d_in[4];
    float* out = (float*)d_out;

    int n = in_sizes[0] / IN_DIM;   // 50000
    int e = in_sizes[3];            // 800000
    int scan_blocks = (n + 1023) / 1024;   // 49

    void* degPtr = nullptr;
    cudaGetSymbolAddress(&degPtr, g_deg);
    cudaMemsetAsync(degPtr, 0, n * sizeof(int));

    k_count_deg<<<(e + 255) / 256, 256>>>(dst, e);
    k_scan1<<<scan_blocks, 256>>>(n);
    k_scan2<<<1, 64>>>(scan_blocks);
    k_scan3<<<(n + 255) / 256, 256>>>(n);
    k_fill<<<(e + 255) / 256, 256>>>(src, dst, e);
    k_gemm<<<(n + BM - 1) / BM, 256>>>(X, W, b, n);
    k_gather<<<(n * 16 + 255) / 256, 256>>>(out, n);
}

// round 6
// speedup vs baseline: 3.2664x; 1.1026x over previous
#include <cuda_runtime.h>
#include <cuda_bf16.h>
#include <cstdint>

#define N_NODES 50000
#define N_EDGES 800000
#define IN_DIM 256
#define OUT_DIM 64

// Scratch
__device__ float4 g_H4[(N_NODES + 128) * OUT_DIM / 4];  // H = X@W^T + b (unscaled)
__device__ int    g_deg[N_NODES];
__device__ float  g_dinv[N_NODES];
__device__ int    g_rowptr[N_NODES];
__device__ int    g_cursor[N_NODES];
__device__ int    g_esrc[N_EDGES];
__device__ int    g_ctr;

// ---------------------------------------------------------------------------
// degree histogram over dst (g_deg zeroed via memset; thread 0 zeroes g_ctr)
__global__ void k_count_deg(const int* __restrict__ dst, int e) {
    int i = blockIdx.x * blockDim.x + threadIdx.x;
    if (i == 0) g_ctr = 0;
    if (i < e) atomicAdd(&g_deg[dst[i]], 1);
}

// CSR slot allocation (order-free): rowptr[i] = atomicAdd(ctr, deg[i]),
// via warp shuffle-scan + 1 atomic per warp. Also computes dinv.
__global__ void k_alloc(int n) {
    int i = blockIdx.x * blockDim.x + threadIdx.x;
    int lane = threadIdx.x & 31;
    int d = (i < n) ? g_deg[i] : 0;
    int pre = d;
#pragma unroll
    for (int off = 1; off < 32; off <<= 1) {
        int x = __shfl_up_sync(0xFFFFFFFFu, pre, off);
        if (lane >= off) pre += x;
    }
    int ex  = pre - d;                       // exclusive prefix within warp
    int tot = __shfl_sync(0xFFFFFFFFu, pre, 31);
    int base = 0;
    if (lane == 31) base = atomicAdd(&g_ctr, tot);
    base = __shfl_sync(0xFFFFFFFFu, base, 31);
    if (i < n) {
        int rp = base + ex;
        g_rowptr[i] = rp;
        g_cursor[i] = rp;
        g_dinv[i] = rsqrtf((float)d + 1.0f);
    }
}

// CSR fill: bucket edge sources by dst
__global__ void k_fill(const int* __restrict__ src, const int* __restrict__ dst, int e) {
    int i = blockIdx.x * blockDim.x + threadIdx.x;
    if (i >= e) return;
    int d = dst[i];
    int pos = atomicAdd(&g_cursor[d], 1);
    g_esrc[pos] = src[i];
}

// ---------------------------------------------------------------------------
// GEMM: H = X @ W^T + b   (no dinv -> independent of CSR branch)
// 256 threads, block tile 128x64, per-thread 8 rows x 4 cols. K chunked by 32.
#define BM 128
#define BN 64
#define KC 32

__global__ __launch_bounds__(256) void k_gemm(const float* __restrict__ X,
                                              const float* __restrict__ W,
                                              const float* __restrict__ b, int n) {
    __shared__ float Xs[KC][BM + 4];
    __shared__ float Ws[KC][BN + 4];

    int tid = threadIdx.x;
    int tx = tid & 15;
    int ty = tid >> 4;
    int rowBase = ty * 8;
    int colBase = tx * 4;
    int nodeBase = blockIdx.x * BM;

    float acc[8][4];
#pragma unroll
    for (int i = 0; i < 8; i++)
#pragma unroll
        for (int j = 0; j < 4; j++) acc[i][j] = 0.0f;

    for (int kb = 0; kb < IN_DIM; kb += KC) {
        {
            int xrow = tid >> 1;
            int xk = (tid & 1) * 16;
            int grow = nodeBase + xrow;
            bool ok = grow < n;
            const float4* xr = (const float4*)&X[(long long)grow * IN_DIM + kb + xk];
#pragma unroll
            for (int j = 0; j < 4; j++) {
                float4 v = ok ? xr[j] : make_float4(0.f, 0.f, 0.f, 0.f);
                Xs[xk + j * 4 + 0][xrow] = v.x;
                Xs[xk + j * 4 + 1][xrow] = v.y;
                Xs[xk + j * 4 + 2][xrow] = v.z;
                Xs[xk + j * 4 + 3][xrow] = v.w;
            }
        }
        {
            int wcol = tid >> 2;
            int wk = (tid & 3) * 8;
            const float4* wr = (const float4*)&W[wcol * IN_DIM + kb + wk];
#pragma unroll
            for (int j = 0; j < 2; j++) {
                float4 v = wr[j];
                Ws[wk + j * 4 + 0][wcol] = v.x;
                Ws[wk + j * 4 + 1][wcol] = v.y;
                Ws[wk + j * 4 + 2][wcol] = v.z;
                Ws[wk + j * 4 + 3][wcol] = v.w;
            }
        }
        __syncthreads();

#pragma unroll
        for (int k = 0; k < KC; k++) {
            float4 xa = *(const float4*)&Xs[k][rowBase];
            float4 xb = *(const float4*)&Xs[k][rowBase + 4];
            float4 wa = *(const float4*)&Ws[k][colBase];
            float xv[8] = {xa.x, xa.y, xa.z, xa.w, xb.x, xb.y, xb.z, xb.w};
            float wv[4] = {wa.x, wa.y, wa.z, wa.w};
#pragma unroll
            for (int i = 0; i < 8; i++)
#pragma unroll
                for (int j = 0; j < 4; j++)
                    acc[i][j] += xv[i] * wv[j];
        }
        __syncthreads();
    }

    float4 bva = *(const float4*)&b[colBase];
    float bv[4] = {bva.x, bva.y, bva.z, bva.w};
    float* H = (float*)g_H4;
#pragma unroll
    for (int i = 0; i < 8; i++) {
        int node = nodeBase + rowBase + i;
        if (node >= n) break;
        float4 h;
        h.x = acc[i][0] + bv[0];
        h.y = acc[i][1] + bv[1];
        h.z = acc[i][2] + bv[2];
        h.w = acc[i][3] + bv[3];
        *(float4*)&H[(long long)node * OUT_DIM + colBase] = h;
    }
}

// ---------------------------------------------------------------------------
// threefry: JAX partitionable 32-bit path: bits = out0 ^ out1, counter (0, i)
__device__ __forceinline__ uint32_t threefry_xor(uint32_t c0, uint32_t c1) {
    const uint32_t k0 = 0u, k1 = 42u;
    const uint32_t k2 = k0 ^ k1 ^ 0x1BD11BDAu;
    uint32_t x0 = c0 + k0;
    uint32_t x1 = c1 + k1;
#define TF_RND(r) { x0 += x1; x1 = (x1 << (r)) | (x1 >> (32 - (r))); x1 ^= x0; }
    TF_RND(13) TF_RND(15) TF_RND(26) TF_RND(6)
    x0 += k1; x1 += k2 + 1u;
    TF_RND(17) TF_RND(29) TF_RND(16) TF_RND(24)
    x0 += k2; x1 += k0 + 2u;
    TF_RND(13) TF_RND(15) TF_RND(26) TF_RND(6)
    x0 += k0; x1 += k1 + 3u;
    TF_RND(17) TF_RND(29) TF_RND(16) TF_RND(24)
    x0 += k1; x1 += k2 + 4u;
    TF_RND(13) TF_RND(15) TF_RND(26) TF_RND(6)
    x0 += k2; x1 += k0 + 5u;
#undef TF_RND
    return x0 ^ x1;
}

// ---------------------------------------------------------------------------
// Gather + self-loop + normalization + ReLU + dropout, fully fused.
// 16 threads per node, each owns one float4 column chunk.
// acc = dinv[d] * (dinv[d]*H[d] + sum_e dinv[s]*H[s])
__global__ __launch_bounds__(256) void k_gather(float* __restrict__ out, int n) {
    int t = blockIdx.x * blockDim.x + threadIdx.x;
    int node = t >> 4;
    int q = t & 15;
    if (node >= n) return;

    const float4* H = g_H4;
    int beg = g_rowptr[node];
    int cnt = g_deg[node];
    int end = beg + cnt;
    float dv = g_dinv[node];

    float4 self = H[node * 16 + q];
    float4 acc = make_float4(self.x * dv, self.y * dv, self.z * dv, self.w * dv);

    int j = beg;
    for (; j + 4 <= end; j += 4) {
        int s0 = g_esrc[j + 0];
        int s1 = g_esrc[j + 1];
        int s2 = g_esrc[j + 2];
        int s3 = g_esrc[j + 3];
        float w0 = g_dinv[s0];
        float w1 = g_dinv[s1];
        float w2 = g_dinv[s2];
        float w3 = g_dinv[s3];
        float4 a0 = H[s0 * 16 + q];
        float4 a1 = H[s1 * 16 + q];
        float4 a2 = H[s2 * 16 + q];
        float4 a3 = H[s3 * 16 + q];
        acc.x += a0.x * w0 + a1.x * w1 + a2.x * w2 + a3.x * w3;
        acc.y += a0.y * w0 + a1.y * w1 + a2.y * w2 + a3.y * w3;
        acc.z += a0.z * w0 + a1.z * w1 + a2.z * w2 + a3.z * w3;
        acc.w += a0.w * w0 + a1.w * w1 + a2.w * w2 + a3.w * w3;
    }
    for (; j < end; j++) {
        int s = g_esrc[j];
        float w = g_dinv[s];
        float4 a = H[s * 16 + q];
        acc.x += a.x * w; acc.y += a.y * w; acc.z += a.z * w; acc.w += a.w * w;
    }

    acc.x *= dv; acc.y *= dv; acc.z *= dv; acc.w *= dv;

    uint32_t base = (uint32_t)(node * OUT_DIM + q * 4);
    uint32_t r0 = threefry_xor(0u, base + 0u);
    uint32_t r1 = threefry_xor(0u, base + 1u);
    uint32_t r2 = threefry_xor(0u, base + 2u);
    uint32_t r3 = threefry_xor(0u, base + 3u);
    float4 o;
    o.x = (r0 & 0x80000000u) ? 0.0f : 2.0f * fmaxf(acc.x, 0.0f);
    o.y = (r1 & 0x80000000u) ? 0.0f : 2.0f * fmaxf(acc.y, 0.0f);
    o.z = (r2 & 0x80000000u) ? 0.0f : 2.0f * fmaxf(acc.z, 0.0f);
    o.w = (r3 & 0x80000000u) ? 0.0f : 2.0f * fmaxf(acc.w, 0.0f);
    ((float4*)out)[node * 16 + q] = o;
}

// ---------------------------------------------------------------------------
extern "C" void kernel_launch(void* const* d_in, const int* in_sizes, int n_in,
                              void* d_out, int out_size) {
    const float* X  = (const float*)d_in[0];
    const float* W  = (const float*)d_in[1];
    const float* b  = (const float*)d_in[2];
    const int* src  = (const int*)d_in[3];
    const int* dst  = (const int*)d_in[4];
    float* out = (float*)d_out;

    int n = in_sizes[0] / IN_DIM;   // 50000
    int e = in_sizes[3];            // 800000

    void* degPtr = nullptr;
    cudaGetSymbolAddress(&degPtr, g_deg);

    // Lazily-created side stream + events for a forked capture branch.
    static cudaStream_t s2 = nullptr;
    static cudaEvent_t evFork = nullptr, evJoin = nullptr;
    static bool tried = false;
    if (!tried) {
        tried = true;
        if (cudaStreamCreateWithFlags(&s2, cudaStreamNonBlocking) != cudaSuccess) s2 = nullptr;
        if (s2) {
            if (cudaEventCreateWithFlags(&evFork, cudaEventDisableTiming) != cudaSuccess ||
                cudaEventCreateWithFlags(&evJoin, cudaEventDisableTiming) != cudaSuccess) {
                s2 = nullptr;
            }
        }
    }

    if (s2) {
        // Fork: CSR build on s2, GEMM on main (legacy) stream, join before gather.
        cudaEventRecord(evFork, 0);
        cudaStreamWaitEvent(s2, evFork, 0);

        cudaMemsetAsync(degPtr, 0, n * sizeof(int), s2);
        k_count_deg<<<(e + 255) / 256, 256, 0, s2>>>(dst, e);
        k_alloc<<<(n + 255) / 256, 256, 0, s2>>>(n);
        k_fill<<<(e + 255) / 256, 256, 0, s2>>>(src, dst, e);
        cudaEventRecord(evJoin, s2);

        k_gemm<<<(n + BM - 1) / BM, 256>>>(X, W, b, n);

        cudaStreamWaitEvent(0, evJoin, 0);
        k_gather<<<(n * 16 + 255) / 256, 256>>>(out, n);
    } else {
        // Serial fallback
        cudaMemsetAsync(degPtr, 0, n * sizeof(int));
        k_count_deg<<<(e + 255) / 256, 256>>>(dst, e);
        k_alloc<<<(n + 255) / 256, 256>>>(n);
        k_fill<<<(e + 255) / 256, 256>>>(src, dst, e);
        k_gemm<<<(n + BM - 1) / BM, 256>>>(X, W, b, n);
        k_gather<<<(n * 16 + 255) / 256, 256>>>(out, n);
    }
}

// round 7
// speedup vs baseline: 3.3699x; 1.0317x over previous
#include <cuda_runtime.h>
#include <cuda_bf16.h>
#include <cstdint>

#define N_NODES 50000
#define N_EDGES 800000
#define IN_DIM 256
#define OUT_DIM 64

// Scratch
__device__ float4 g_H4[(N_NODES + 128) * OUT_DIM / 4];  // H = X@W^T + b (unscaled)
__device__ int    g_deg[N_NODES];
__device__ float  g_dinv[N_NODES];
__device__ int    g_rowptr[N_NODES];
__device__ int    g_cursor[N_NODES];
__device__ int    g_esrc[N_EDGES];
__device__ int    g_ctr;

// ---------------------------------------------------------------------------
// degree histogram over dst (g_deg zeroed via memset; thread 0 zeroes g_ctr)
__global__ void k_count_deg(const int* __restrict__ dst, int e) {
    int i = blockIdx.x * blockDim.x + threadIdx.x;
    if (i == 0) g_ctr = 0;
    if (i < e) atomicAdd(&g_deg[dst[i]], 1);
}

// CSR slot allocation (order-free): rowptr[i] = atomicAdd(ctr, deg[i]),
// via warp shuffle-scan + 1 atomic per warp. Also computes dinv.
__global__ void k_alloc(int n) {
    int i = blockIdx.x * blockDim.x + threadIdx.x;
    int lane = threadIdx.x & 31;
    int d = (i < n) ? g_deg[i] : 0;
    int pre = d;
#pragma unroll
    for (int off = 1; off < 32; off <<= 1) {
        int x = __shfl_up_sync(0xFFFFFFFFu, pre, off);
        if (lane >= off) pre += x;
    }
    int ex  = pre - d;
    int tot = __shfl_sync(0xFFFFFFFFu, pre, 31);
    int base = 0;
    if (lane == 31) base = atomicAdd(&g_ctr, tot);
    base = __shfl_sync(0xFFFFFFFFu, base, 31);
    if (i < n) {
        int rp = base + ex;
        g_rowptr[i] = rp;
        g_cursor[i] = rp;
        g_dinv[i] = rsqrtf((float)d + 1.0f);
    }
}

// CSR fill: bucket edge sources by dst
__global__ void k_fill(const int* __restrict__ src, const int* __restrict__ dst, int e) {
    int i = blockIdx.x * blockDim.x + threadIdx.x;
    if (i >= e) return;
    int d = dst[i];
    int pos = atomicAdd(&g_cursor[d], 1);
    g_esrc[pos] = src[i];
}

// ---------------------------------------------------------------------------
// Packed fp32x2 helpers (Blackwell FFMA2; only reachable via PTX)
__device__ __forceinline__ uint64_t pack2(float lo, float hi) {
    uint64_t r;
    asm("mov.b64 %0, {%1, %2};" : "=l"(r) : "f"(lo), "f"(hi));
    return r;
}
__device__ __forceinline__ void unpack2(uint64_t v, float& lo, float& hi) {
    asm("mov.b64 {%0, %1}, %2;" : "=f"(lo), "=f"(hi) : "l"(v));
}
__device__ __forceinline__ void ffma2(uint64_t& acc, uint64_t a, uint64_t b) {
    asm("fma.rn.f32x2 %0, %1, %2, %0;" : "+l"(acc) : "l"(a), "l"(b));
}

// ---------------------------------------------------------------------------
// GEMM: H = X @ W^T + b   (no dinv -> independent of CSR branch)
// 256 threads, block tile 128x64, per-thread 8 rows x 4 cols, row-paired
// f32x2 accumulators. K chunked by 32.
#define BM 128
#define BN 64
#define KC 32

__global__ __launch_bounds__(256) void k_gemm(const float* __restrict__ X,
                                              const float* __restrict__ W,
                                              const float* __restrict__ b, int n) {
    __shared__ float Xs[KC][BM + 4];
    __shared__ float Ws[KC][BN + 4];

    int tid = threadIdx.x;
    int tx = tid & 15;
    int ty = tid >> 4;
    int rowBase = ty * 8;
    int colBase = tx * 4;
    int nodeBase = blockIdx.x * BM;

    // acc2[p][j]: rows (rowBase+2p, rowBase+2p+1), col (colBase+j)
    uint64_t acc2[4][4];
#pragma unroll
    for (int p = 0; p < 4; p++)
#pragma unroll
        for (int j = 0; j < 4; j++) acc2[p][j] = 0ull;

    for (int kb = 0; kb < IN_DIM; kb += KC) {
        {
            int xrow = tid >> 1;
            int xk = (tid & 1) * 16;
            int grow = nodeBase + xrow;
            bool ok = grow < n;
            const float4* xr = (const float4*)&X[(long long)grow * IN_DIM + kb + xk];
#pragma unroll
            for (int j = 0; j < 4; j++) {
                float4 v = ok ? xr[j] : make_float4(0.f, 0.f, 0.f, 0.f);
                Xs[xk + j * 4 + 0][xrow] = v.x;
                Xs[xk + j * 4 + 1][xrow] = v.y;
                Xs[xk + j * 4 + 2][xrow] = v.z;
                Xs[xk + j * 4 + 3][xrow] = v.w;
            }
        }
        {
            int wcol = tid >> 2;
            int wk = (tid & 3) * 8;
            const float4* wr = (const float4*)&W[wcol * IN_DIM + kb + wk];
#pragma unroll
            for (int j = 0; j < 2; j++) {
                float4 v = wr[j];
                Ws[wk + j * 4 + 0][wcol] = v.x;
                Ws[wk + j * 4 + 1][wcol] = v.y;
                Ws[wk + j * 4 + 2][wcol] = v.z;
                Ws[wk + j * 4 + 3][wcol] = v.w;
            }
        }
        __syncthreads();

#pragma unroll
        for (int k = 0; k < KC; k++) {
            float4 xa = *(const float4*)&Xs[k][rowBase];
            float4 xb = *(const float4*)&Xs[k][rowBase + 4];
            float4 wa = *(const float4*)&Ws[k][colBase];
            // row pairs (adjacent float4 lanes -> ptxas register pairs)
            uint64_t xp0 = pack2(xa.x, xa.y);
            uint64_t xp1 = pack2(xa.z, xa.w);
            uint64_t xp2 = pack2(xb.x, xb.y);
            uint64_t xp3 = pack2(xb.z, xb.w);
            // duplicated W scalars
            uint64_t wd0 = pack2(wa.x, wa.x);
            uint64_t wd1 = pack2(wa.y, wa.y);
            uint64_t wd2 = pack2(wa.z, wa.z);
            uint64_t wd3 = pack2(wa.w, wa.w);
            ffma2(acc2[0][0], xp0, wd0); ffma2(acc2[0][1], xp0, wd1);
            ffma2(acc2[0][2], xp0, wd2); ffma2(acc2[0][3], xp0, wd3);
            ffma2(acc2[1][0], xp1, wd0); ffma2(acc2[1][1], xp1, wd1);
            ffma2(acc2[1][2], xp1, wd2); ffma2(acc2[1][3], xp1, wd3);
            ffma2(acc2[2][0], xp2, wd0); ffma2(acc2[2][1], xp2, wd1);
            ffma2(acc2[2][2], xp2, wd2); ffma2(acc2[2][3], xp2, wd3);
            ffma2(acc2[3][0], xp3, wd0); ffma2(acc2[3][1], xp3, wd1);
            ffma2(acc2[3][2], xp3, wd2); ffma2(acc2[3][3], xp3, wd3);
        }
        __syncthreads();
    }

    float4 bva = *(const float4*)&b[colBase];
    float bv[4] = {bva.x, bva.y, bva.z, bva.w};
    float* H = (float*)g_H4;
#pragma unroll
    for (int p = 0; p < 4; p++) {
        float lo[4], hi[4];
#pragma unroll
        for (int j = 0; j < 4; j++) unpack2(acc2[p][j], lo[j], hi[j]);
        int node0 = nodeBase + rowBase + 2 * p;
        if (node0 < n) {
            float4 h;
            h.x = lo[0] + bv[0]; h.y = lo[1] + bv[1];
            h.z = lo[2] + bv[2]; h.w = lo[3] + bv[3];
            *(float4*)&H[(long long)node0 * OUT_DIM + colBase] = h;
        }
        if (node0 + 1 < n) {
            float4 h;
            h.x = hi[0] + bv[0]; h.y = hi[1] + bv[1];
            h.z = hi[2] + bv[2]; h.w = hi[3] + bv[3];
            *(float4*)&H[(long long)(node0 + 1) * OUT_DIM + colBase] = h;
        }
    }
}

// ---------------------------------------------------------------------------
// threefry: JAX partitionable 32-bit path: bits = out0 ^ out1, counter (0, i)
__device__ __forceinline__ uint32_t threefry_xor(uint32_t c0, uint32_t c1) {
    const uint32_t k0 = 0u, k1 = 42u;
    const uint32_t k2 = k0 ^ k1 ^ 0x1BD11BDAu;
    uint32_t x0 = c0 + k0;
    uint32_t x1 = c1 + k1;
#define TF_RND(r) { x0 += x1; x1 = (x1 << (r)) | (x1 >> (32 - (r))); x1 ^= x0; }
    TF_RND(13) TF_RND(15) TF_RND(26) TF_RND(6)
    x0 += k1; x1 += k2 + 1u;
    TF_RND(17) TF_RND(29) TF_RND(16) TF_RND(24)
    x0 += k2; x1 += k0 + 2u;
    TF_RND(13) TF_RND(15) TF_RND(26) TF_RND(6)
    x0 += k0; x1 += k1 + 3u;
    TF_RND(17) TF_RND(29) TF_RND(16) TF_RND(24)
    x0 += k1; x1 += k2 + 4u;
    TF_RND(13) TF_RND(15) TF_RND(26) TF_RND(6)
    x0 += k2; x1 += k0 + 5u;
#undef TF_RND
    return x0 ^ x1;
}

// ---------------------------------------------------------------------------
// Gather + self-loop + normalization + ReLU + dropout, fully fused.
// 16 threads per node, each owns one float4 column chunk.
// acc = dinv[d] * (dinv[d]*H[d] + sum_e dinv[s]*H[s])
__global__ __launch_bounds__(256) void k_gather(float* __restrict__ out, int n) {
    int t = blockIdx.x * blockDim.x + threadIdx.x;
    int node = t >> 4;
    int q = t & 15;
    if (node >= n) return;

    const float4* H = g_H4;
    int beg = g_rowptr[node];
    int cnt = g_deg[node];
    int end = beg + cnt;
    float dv = g_dinv[node];

    float4 self = H[node * 16 + q];
    float4 acc = make_float4(self.x * dv, self.y * dv, self.z * dv, self.w * dv);

    int j = beg;
    for (; j + 4 <= end; j += 4) {
        int s0 = g_esrc[j + 0];
        int s1 = g_esrc[j + 1];
        int s2 = g_esrc[j + 2];
        int s3 = g_esrc[j + 3];
        float w0 = g_dinv[s0];
        float w1 = g_dinv[s1];
        float w2 = g_dinv[s2];
        float w3 = g_dinv[s3];
        float4 a0 = H[s0 * 16 + q];
        float4 a1 = H[s1 * 16 + q];
        float4 a2 = H[s2 * 16 + q];
        float4 a3 = H[s3 * 16 + q];
        acc.x += a0.x * w0 + a1.x * w1 + a2.x * w2 + a3.x * w3;
        acc.y += a0.y * w0 + a1.y * w1 + a2.y * w2 + a3.y * w3;
        acc.z += a0.z * w0 + a1.z * w1 + a2.z * w2 + a3.z * w3;
        acc.w += a0.w * w0 + a1.w * w1 + a2.w * w2 + a3.w * w3;
    }
    for (; j < end; j++) {
        int s = g_esrc[j];
        float w = g_dinv[s];
        float4 a = H[s * 16 + q];
        acc.x += a.x * w; acc.y += a.y * w; acc.z += a.z * w; acc.w += a.w * w;
    }

    acc.x *= dv; acc.y *= dv; acc.z *= dv; acc.w *= dv;

    uint32_t base = (uint32_t)(node * OUT_DIM + q * 4);
    uint32_t r0 = threefry_xor(0u, base + 0u);
    uint32_t r1 = threefry_xor(0u, base + 1u);
    uint32_t r2 = threefry_xor(0u, base + 2u);
    uint32_t r3 = threefry_xor(0u, base + 3u);
    float4 o;
    o.x = (r0 & 0x80000000u) ? 0.0f : 2.0f * fmaxf(acc.x, 0.0f);
    o.y = (r1 & 0x80000000u) ? 0.0f : 2.0f * fmaxf(acc.y, 0.0f);
    o.z = (r2 & 0x80000000u) ? 0.0f : 2.0f * fmaxf(acc.z, 0.0f);
    o.w = (r3 & 0x80000000u) ? 0.0f : 2.0f * fmaxf(acc.w, 0.0f);
    ((float4*)out)[node * 16 + q] = o;
}

// ---------------------------------------------------------------------------
extern "C" void kernel_launch(void* const* d_in, const int* in_sizes, int n_in,
                              void* d_out, int out_size) {
    const float* X  = (const float*)d_in[0];
    const float* W  = (const float*)d_in[1];
    const float* b  = (const float*)d_in[2];
    const int* src  = (const int*)d_in[3];
    const int* dst  = (const int*)d_in[4];
    float* out = (float*)d_out;

    int n = in_sizes[0] / IN_DIM;   // 50000
    int e = in_sizes[3];            // 800000

    void* degPtr = nullptr;
    cudaGetSymbolAddress(&degPtr, g_deg);

    static cudaStream_t s2 = nullptr;
    static cudaEvent_t evFork = nullptr, evJoin = nullptr;
    static bool tried = false;
    if (!tried) {
        tried = true;
        if (cudaStreamCreateWithFlags(&s2, cudaStreamNonBlocking) != cudaSuccess) s2 = nullptr;
        if (s2) {
            if (cudaEventCreateWithFlags(&evFork, cudaEventDisableTiming) != cudaSuccess ||
                cudaEventCreateWithFlags(&evJoin, cudaEventDisableTiming) != cudaSuccess) {
                s2 = nullptr;
            }
        }
    }

    if (s2) {
        cudaEventRecord(evFork, 0);
        cudaStreamWaitEvent(s2, evFork, 0);

        cudaMemsetAsync(degPtr, 0, n * sizeof(int), s2);
        k_count_deg<<<(e + 255) / 256, 256, 0, s2>>>(dst, e);
        k_alloc<<<(n + 255) / 256, 256, 0, s2>>>(n);
        k_fill<<<(e + 255) / 256, 256, 0, s2>>>(src, dst, e);
        cudaEventRecord(evJoin, s2);

        k_gemm<<<(n + BM - 1) / BM, 256>>>(X, W, b, n);

        cudaStreamWaitEvent(0, evJoin, 0);
        k_gather<<<(n * 16 + 255) / 256, 256>>>(out, n);
    } else {
        cudaMemsetAsync(degPtr, 0, n * sizeof(int));
        k_count_deg<<<(e + 255) / 256, 256>>>(dst, e);
        k_alloc<<<(n + 255) / 256, 256>>>(n);
        k_fill<<<(e + 255) / 256, 256>>>(src, dst, e);
        k_gemm<<<(n + BM - 1) / BM, 256>>>(X, W, b, n);
        k_gather<<<(n * 16 + 255) / 256, 256>>>(out, n);
    }
}